// round 12
// baseline (speedup 1.0000x reference)
#include <cuda_runtime.h>
#include <cuda_bf16.h>
#include <cstdint>

#define NB 64
#define CC 32
#define KK 5
#define ADIM 4
#define AHID 256

typedef unsigned long long u64;

// packed f32x2 helpers
#define PACK2(out, lo, hi) \
    asm("mov.b64 %0, {%1, %2};" : "=l"(out) : "r"(lo), "r"(hi))
#define FMA2(acc, a, b) \
    asm("fma.rn.f32x2 %0, %1, %2, %0;" : "+l"(acc) : "l"(a), "l"(b))
#define UNPACK2(lo, hi, in) \
    asm("mov.b64 {%0, %1}, %2;" : "=r"(lo), "=r"(hi) : "l"(in))

__device__ __forceinline__ u64 pack_dup(float v) {
    u64 r; unsigned u = __float_as_uint(v);
    PACK2(r, u, u); return r;
}

__device__ __forceinline__ uint32_t smem_to_u32(const void* p) {
    uint32_t a;
    asm("{ .reg .u64 t; cvta.to.shared.u64 t, %1; cvt.u32.u64 %0, t; }" : "=r"(a) : "l"(p));
    return a;
}
// 4-byte async copy; pred=false -> zero-fill (src still clamped-valid)
__device__ __forceinline__ void cpa4(uint32_t dst, const void* src, bool pred) {
    int sz = pred ? 4 : 0;
    asm volatile("cp.async.ca.shared.global [%0], [%1], 4, %2;"
                 :: "r"(dst), "l"(src), "r"(sz));
}
#define CP_COMMIT() asm volatile("cp.async.commit_group;" ::: "memory")
#define CP_WAIT0()  asm volatile("cp.async.wait_group 0;" ::: "memory")

// ---------------- scratch ----------------
__device__ float g_h1[NB * CC * 128 * 128];
__device__ float g_h2[NB * CC * 64 * 64];
__device__ float g_ker[NB * CC * KK * KK];
__device__ float g_sa[NB * CC * 64 * 64];
__device__ float g_f [NB * CC * 64 * 64];

// =================== action encoder MLP ===================
__global__ void ae_kernel(const float* __restrict__ act,
                          const float* __restrict__ w1, const float* __restrict__ b1,
                          const float* __restrict__ w2, const float* __restrict__ b2) {
    __shared__ float sH[AHID];
    __shared__ float sA[ADIM];
    int n = blockIdx.x, tid = threadIdx.x;
    if (tid < ADIM) sA[tid] = act[n * ADIM + tid];
    __syncthreads();
    float h = b1[tid];
#pragma unroll
    for (int i = 0; i < ADIM; i++) h = fmaf(sA[i], w1[i * AHID + tid], h);
    sH[tid] = fmaxf(h, 0.f);
    __syncthreads();
    for (int o = tid; o < CC * KK * KK; o += 256) {
        float acc = b2[o];
#pragma unroll 8
        for (int j = 0; j < AHID; j++) acc = fmaf(sH[j], w2[j * (CC * KK * KK) + o], acc);
        g_ker[n * (CC * KK * KK) + o] = acc;
    }
}

// =================== conv1: 3->32, k5, s2, p2, NHWC in ===================
__global__ void __launch_bounds__(256, 2)
conv1_kernel(const float* __restrict__ img,
             const float* __restrict__ w, const float* __restrict__ b) {
    __shared__ __align__(16) float sIn[2][3 * 35 * 34];
    __shared__ __align__(16) float sW[75 * 32];
    __shared__ __align__(8) float sB[32];
    int n = blockIdx.z;
    int ox0 = blockIdx.x * 32, oy0 = blockIdx.y * 16;
    int tid = threadIdx.x;

    for (int i = tid; i < 75 * 32; i += 256) {
        int o = i & 31, tap = i >> 5;
        int c = tap / 25, r = tap % 25, kh = r / 5, kw = r % 5;
        sW[i] = w[((o * 3 + c) * 5 + kh) * 5 + kw];
    }
    if (tid < 32) sB[tid] = b[tid];

    int iy0 = oy0 * 2 - 2, ix0 = ox0 * 2 - 2;
    for (int i = tid; i < 3 * 35 * 67; i += 256) {
        int c = i / (35 * 67), r = i % (35 * 67);
        int iy = r / 67, ix = r % 67;
        int gy = iy0 + iy, gx = ix0 + ix;
        float v = 0.f;
        if ((unsigned)gy < 256u && (unsigned)gx < 256u)
            v = img[((n * 256 + gy) * 256 + gx) * 3 + c];
        sIn[ix & 1][c * 1190 + iy * 34 + (ix >> 1)] = v;
    }
    __syncthreads();

    int ox = tid & 31, oyr = tid >> 5;
    u64 accA[16], accB[16];
    const u64* sB2 = (const u64*)sB;
#pragma unroll
    for (int o = 0; o < 16; o++) { accA[o] = sB2[o]; accB[o] = sB2[o]; }

    for (int c = 0; c < 3; c++)
        for (int kh = 0; kh < 5; kh++) {
            int base = c * 1190 + (2 * oyr + kh) * 34 + ox;
            const float* pl[2] = { &sIn[0][base], &sIn[1][base] };
#pragma unroll
            for (int kw = 0; kw < 5; kw++) {
                float fA = pl[kw & 1][kw >> 1];
                float fB = pl[kw & 1][(kw >> 1) + 544];
                u64 vA2 = pack_dup(fA);
                u64 vB2 = pack_dup(fB);
                const ulonglong2* wq =
                    (const ulonglong2*)&sW[((c * 5 + kh) * 5 + kw) * 32];
#pragma unroll
                for (int o2 = 0; o2 < 8; o2++) {
                    ulonglong2 ww = wq[o2];
                    FMA2(accA[2 * o2], vA2, ww.x);
                    FMA2(accA[2 * o2 + 1], vA2, ww.y);
                    FMA2(accB[2 * o2], vB2, ww.x);
                    FMA2(accB[2 * o2 + 1], vB2, ww.y);
                }
            }
        }

    int gyA = oy0 + oyr, gyB = gyA + 8, gx = ox0 + ox;
#pragma unroll
    for (int o = 0; o < 16; o++) {
        unsigned lo, hi;
        UNPACK2(lo, hi, accA[o]);
        g_h1[((n * 32 + 2 * o) * 128 + gyA) * 128 + gx] = fmaxf(__uint_as_float(lo), 0.f);
        g_h1[((n * 32 + 2 * o + 1) * 128 + gyA) * 128 + gx] = fmaxf(__uint_as_float(hi), 0.f);
        UNPACK2(lo, hi, accB[o]);
        g_h1[((n * 32 + 2 * o) * 128 + gyB) * 128 + gx] = fmaxf(__uint_as_float(lo), 0.f);
        g_h1[((n * 32 + 2 * o + 1) * 128 + gyB) * 128 + gx] = fmaxf(__uint_as_float(hi), 0.f);
    }
}

// =================== conv2: 32->32, k5, s2, p2 ===================
// cp.async double-buffer, 2 ic per stage (16 barriers), parity-split halo.
// dyn smem floats: sIn [buf2][icl2][par2][1190]=9520 | sW [buf2][icl2][800]=3200 | sB 32
#define C2_SMEM ((9520 + 3200 + 32) * 4)
__global__ void __launch_bounds__(256, 2)
conv2_kernel(const float* __restrict__ w, const float* __restrict__ b) {
    extern __shared__ __align__(16) float c2sm[];
    float* sIn = c2sm;
    float* sW = c2sm + 9520;
    float* sB = c2sm + 12720;
    uint32_t sIn_u = smem_to_u32(sIn);
    uint32_t sW_u = smem_to_u32(sW);
    int n = blockIdx.z;
    int ox0 = blockIdx.x * 32, oy0 = blockIdx.y * 16;
    int tid = threadIdx.x;
    int ox = tid & 31, oyr = tid >> 5;
    if (tid < 32) sB[tid] = b[tid];

    int iy0 = oy0 * 2 - 2, ix0 = ox0 * 2 - 2;

    // ---- stage issue: inputs (2 ic, parity-scattered) + weights via cp.async ----
    auto issue_stage = [&](int icp, int buf) {
#pragma unroll
        for (int icl = 0; icl < 2; icl++) {
            const float* src = &g_h1[((size_t)n * 32 + 2 * icp + icl) * 16384];
#pragma unroll
            for (int j = 0; j < 10; j++) {
                int i = tid + j * 256;
                if (i < 2345) {
                    int iy = i / 67, ix = i % 67;
                    int gy = iy0 + iy, gx = ix0 + ix;
                    bool ok = (unsigned)gy < 128u && (unsigned)gx < 128u;
                    int gyc = ok ? gy : 0, gxc = ok ? gx : 0;
                    uint32_t dst = sIn_u + 4u * (buf * 4760 + icl * 2380 +
                                                 (ix & 1) * 1190 + iy * 34 + (ix >> 1));
                    cpa4(dst, src + gyc * 128 + gxc, ok);
                }
            }
        }
#pragma unroll
        for (int j = 0; j < 7; j++) {
            int i = tid + j * 256;
            if (i < 1600) {
                int icl = i >= 800 ? 1 : 0, r = i - icl * 800;
                int o = r & 31, tap = r >> 5;
                uint32_t dst = sW_u + 4u * (buf * 1600 + icl * 800 + r);
                cpa4(dst, &w[(o * 32 + 2 * icp + icl) * 25 + tap], true);
            }
        }
    };

    // prologue
    issue_stage(0, 0);
    CP_COMMIT();
    CP_WAIT0();
    __syncthreads();

    u64 accA[16], accB[16];
    const u64* sB2 = (const u64*)sB;
#pragma unroll
    for (int o = 0; o < 16; o++) { accA[o] = sB2[o]; accB[o] = sB2[o]; }

    for (int icp = 0; icp < 16; icp++) {
        int buf = icp & 1;
        if (icp < 15) { issue_stage(icp + 1, 1 - buf); CP_COMMIT(); }
#pragma unroll
        for (int icl = 0; icl < 2; icl++) {
            const float* inb = &sIn[buf * 4760 + icl * 2380];
            const float* wb = &sW[buf * 1600 + icl * 800];
#pragma unroll
            for (int kh = 0; kh < 5; kh++) {
                int base = (2 * oyr + kh) * 34 + ox;
                const float* pl[2] = { inb + base, inb + 1190 + base };
#pragma unroll
                for (int kw = 0; kw < 5; kw++) {
                    float fA = pl[kw & 1][kw >> 1];
                    float fB = pl[kw & 1][(kw >> 1) + 544];
                    u64 vA2 = pack_dup(fA);
                    u64 vB2 = pack_dup(fB);
                    const ulonglong2* wq = (const ulonglong2*)&wb[(kh * 5 + kw) * 32];
#pragma unroll
                    for (int o2 = 0; o2 < 8; o2++) {
                        ulonglong2 ww = wq[o2];
                        FMA2(accA[2 * o2], vA2, ww.x);
                        FMA2(accA[2 * o2 + 1], vA2, ww.y);
                        FMA2(accB[2 * o2], vB2, ww.x);
                        FMA2(accB[2 * o2 + 1], vB2, ww.y);
                    }
                }
            }
        }
        if (icp < 15) { CP_WAIT0(); }
        __syncthreads();
    }

    int gyA = oy0 + oyr, gyB = gyA + 8, gx = ox0 + ox;
#pragma unroll
    for (int o = 0; o < 16; o++) {
        unsigned lo, hi;
        UNPACK2(lo, hi, accA[o]);
        g_h2[((n * 32 + 2 * o) * 64 + gyA) * 64 + gx] = fmaxf(__uint_as_float(lo), 0.f);
        g_h2[((n * 32 + 2 * o + 1) * 64 + gyA) * 64 + gx] = fmaxf(__uint_as_float(hi), 0.f);
        UNPACK2(lo, hi, accB[o]);
        g_h2[((n * 32 + 2 * o) * 64 + gyB) * 64 + gx] = fmaxf(__uint_as_float(lo), 0.f);
        g_h2[((n * 32 + 2 * o + 1) * 64 + gyB) * 64 + gx] = fmaxf(__uint_as_float(hi), 0.f);
    }
}

// =================== cross-conv: depthwise k5 p2, register row-reuse ===================
__global__ void __launch_bounds__(256)
xconv_kernel() {
    __shared__ float sIn[68 * 68];
    __shared__ float sK[25];
    int c = blockIdx.x, n = blockIdx.y;
    int tid = threadIdx.x;
    const float* src = &g_h2[(n * 32 + c) * 4096];
    for (int i = tid; i < 68 * 68; i += 256) {
        int iy = i / 68, ix = i % 68;
        int gy = iy - 2, gx = ix - 2;
        sIn[i] = ((unsigned)gy < 64u && (unsigned)gx < 64u) ? src[gy * 64 + gx] : 0.f;
    }
    if (tid < 25) sK[tid] = g_ker[(n * 32 + c) * 25 + tid];
    __syncthreads();
    float k[25];
#pragma unroll
    for (int t = 0; t < 25; t++) k[t] = sK[t];

    int tx = tid & 63, ty = tid >> 6;
    int ybase = ty * 16;
    float acc[16];
#pragma unroll
    for (int j = 0; j < 16; j++) acc[j] = 0.f;

#pragma unroll
    for (int iy = 0; iy < 20; iy++) {
        const float* row = &sIn[(ybase + iy) * 68 + tx];
        float v0 = row[0], v1 = row[1], v2 = row[2], v3 = row[3], v4 = row[4];
#pragma unroll
        for (int kh = 0; kh < 5; kh++) {
            int j = iy - kh;
            if (j >= 0 && j < 16) {
                float a = acc[j];
                a = fmaf(v0, k[kh * 5 + 0], a);
                a = fmaf(v1, k[kh * 5 + 1], a);
                a = fmaf(v2, k[kh * 5 + 2], a);
                a = fmaf(v3, k[kh * 5 + 3], a);
                a = fmaf(v4, k[kh * 5 + 4], a);
                acc[j] = a;
            }
        }
    }
    float* dst = &g_sa[(n * 32 + c) * 4096 + tx];
#pragma unroll
    for (int j = 0; j < 16; j++) dst[(ybase + j) * 64] = acc[j];
}

// =================== mp1: 32->32, k3, p1, relu ===================
// cp.async double-buffer, 2 ic per stage (16 barriers)
__global__ void __launch_bounds__(256, 2)
mp1_kernel(const float* __restrict__ w, const float* __restrict__ b) {
    __shared__ __align__(16) float sIn[2][2][612];
    __shared__ __align__(16) float sW[2][2][288];
    __shared__ __align__(8) float sB[32];
    uint32_t sIn_u = smem_to_u32(&sIn[0][0][0]);
    uint32_t sW_u = smem_to_u32(&sW[0][0][0]);
    int n = blockIdx.z;
    int ox0 = blockIdx.x * 32, oy0 = blockIdx.y * 16;
    int tid = threadIdx.x;
    int ox = tid & 31, oyr = tid >> 5;
    if (tid < 32) sB[tid] = b[tid];

    int iy0 = oy0 - 1, ix0 = ox0 - 1;

    auto issue_stage = [&](int icp, int buf) {
#pragma unroll
        for (int icl = 0; icl < 2; icl++) {
            const float* src = &g_sa[((size_t)n * 32 + 2 * icp + icl) * 4096];
#pragma unroll
            for (int j = 0; j < 3; j++) {
                int i = tid + j * 256;
                if (i < 612) {
                    int iy = i / 34, ix = i % 34;
                    int gy = iy0 + iy, gx = ix0 + ix;
                    bool ok = (unsigned)gy < 64u && (unsigned)gx < 64u;
                    int gyc = ok ? gy : 0, gxc = ok ? gx : 0;
                    uint32_t dst = sIn_u + 4u * (buf * 1224 + icl * 612 + i);
                    cpa4(dst, src + gyc * 64 + gxc, ok);
                }
            }
        }
#pragma unroll
        for (int j = 0; j < 3; j++) {
            int i = tid + j * 256;
            if (i < 576) {
                int icl = i >= 288 ? 1 : 0, r = i - icl * 288;
                int o = r & 31, tap = r >> 5;
                uint32_t dst = sW_u + 4u * (buf * 576 + icl * 288 + r);
                cpa4(dst, &w[(o * 32 + 2 * icp + icl) * 9 + tap], true);
            }
        }
    };

    issue_stage(0, 0);
    CP_COMMIT();
    CP_WAIT0();
    __syncthreads();

    u64 accA[16], accB[16];
    const u64* sB2 = (const u64*)sB;
#pragma unroll
    for (int o = 0; o < 16; o++) { accA[o] = sB2[o]; accB[o] = sB2[o]; }

    for (int icp = 0; icp < 16; icp++) {
        int buf = icp & 1;
        if (icp < 15) { issue_stage(icp + 1, 1 - buf); CP_COMMIT(); }
#pragma unroll
        for (int icl = 0; icl < 2; icl++) {
            const float* inb = &sIn[buf][icl][0];
            const float* wb = &sW[buf][icl][0];
#pragma unroll
            for (int kh = 0; kh < 3; kh++) {
                const float* rA = inb + (oyr + kh) * 34 + ox;
                const float* rB = rA + 8 * 34;
#pragma unroll
                for (int kw = 0; kw < 3; kw++) {
                    u64 vA2 = pack_dup(rA[kw]);
                    u64 vB2 = pack_dup(rB[kw]);
                    const ulonglong2* wq = (const ulonglong2*)&wb[(kh * 3 + kw) * 32];
#pragma unroll
                    for (int o2 = 0; o2 < 8; o2++) {
                        ulonglong2 ww = wq[o2];
                        FMA2(accA[2 * o2], vA2, ww.x);
                        FMA2(accA[2 * o2 + 1], vA2, ww.y);
                        FMA2(accB[2 * o2], vB2, ww.x);
                        FMA2(accB[2 * o2 + 1], vB2, ww.y);
                    }
                }
            }
        }
        if (icp < 15) { CP_WAIT0(); }
        __syncthreads();
    }

    int gyA = oy0 + oyr, gyB = gyA + 8, gx = ox0 + ox;
#pragma unroll
    for (int o = 0; o < 16; o++) {
        unsigned lo, hi;
        UNPACK2(lo, hi, accA[o]);
        g_f[((n * 32 + 2 * o) * 64 + gyA) * 64 + gx] = fmaxf(__uint_as_float(lo), 0.f);
        g_f[((n * 32 + 2 * o + 1) * 64 + gyA) * 64 + gx] = fmaxf(__uint_as_float(hi), 0.f);
        UNPACK2(lo, hi, accB[o]);
        g_f[((n * 32 + 2 * o) * 64 + gyB) * 64 + gx] = fmaxf(__uint_as_float(lo), 0.f);
        g_f[((n * 32 + 2 * o + 1) * 64 + gyB) * 64 + gx] = fmaxf(__uint_as_float(hi), 0.f);
    }
}

// =================== mp2: 32->2, k3, p1 — 64x16 tile, 4 px/thread, single wave ===================
__global__ void __launch_bounds__(256, 2)
mp2_kernel(const float* __restrict__ w, const float* __restrict__ b,
           float* __restrict__ out) {
    __shared__ __align__(8) float sIn[2][18 * 66];
    __shared__ __align__(8) float sW[2][18];
    int n = blockIdx.z;
    int oy0 = blockIdx.y * 16;
    int tid = threadIdx.x;
    int ox = tid & 63, oyr = tid >> 6;

    int iy0 = oy0 - 1;

    float pin[5], pwv;
    {
        const float* src = &g_f[(n * 32 + 0) * 4096];
#pragma unroll
        for (int j = 0; j < 5; j++) {
            int i = tid + j * 256; float v = 0.f;
            if (i < 1188) {
                int iy = i / 66, ix = i % 66;
                int gy = iy0 + iy, gx = ix - 1;
                if ((unsigned)gy < 64u && (unsigned)gx < 64u) v = src[gy * 64 + gx];
            }
            pin[j] = v;
        }
        pwv = (tid < 18) ? w[((tid & 1) * 32 + 0) * 9 + (tid >> 1)] : 0.f;
    }
#pragma unroll
    for (int j = 0; j < 5; j++) { int i = tid + j * 256; if (i < 1188) sIn[0][i] = pin[j]; }
    if (tid < 18) sW[0][tid] = pwv;
    __syncthreads();

    u64 acc[4];
    {
        u64 binit;
        PACK2(binit, __float_as_uint(b[0]), __float_as_uint(b[1]));
#pragma unroll
        for (int k = 0; k < 4; k++) acc[k] = binit;
    }

    for (int ic = 0; ic < 32; ic++) {
        int cur = ic & 1;
        if (ic < 31) {
            const float* src = &g_f[(n * 32 + ic + 1) * 4096];
#pragma unroll
            for (int j = 0; j < 5; j++) {
                int i = tid + j * 256; float v = 0.f;
                if (i < 1188) {
                    int iy = i / 66, ix = i % 66;
                    int gy = iy0 + iy, gx = ix - 1;
                    if ((unsigned)gy < 64u && (unsigned)gx < 64u) v = src[gy * 64 + gx];
                }
                pin[j] = v;
            }
            pwv = (tid < 18) ? w[((tid & 1) * 32 + ic + 1) * 9 + (tid >> 1)] : 0.f;
        }
        const u64* wp2 = (const u64*)&sW[cur][0];
#pragma unroll
        for (int k = 0; k < 4; k++) {
            int rbase = oyr + 4 * k;
#pragma unroll
            for (int kh = 0; kh < 3; kh++) {
                const float* row = &sIn[cur][(rbase + kh) * 66 + ox];
#pragma unroll
                for (int kw = 0; kw < 3; kw++)
                    FMA2(acc[k], pack_dup(row[kw]), wp2[kh * 3 + kw]);
            }
        }
        if (ic < 31) {
#pragma unroll
            for (int j = 0; j < 5; j++) { int i = tid + j * 256; if (i < 1188) sIn[1 - cur][i] = pin[j]; }
            if (tid < 18) sW[1 - cur][tid] = pwv;
        }
        __syncthreads();
    }

#pragma unroll
    for (int k = 0; k < 4; k++) {
        int gy = oy0 + oyr + 4 * k;
        unsigned lo, hi;
        UNPACK2(lo, hi, acc[k]);
        out[((n * 2 + 0) * 64 + gy) * 64 + ox] = __uint_as_float(lo);
        out[((n * 2 + 1) * 64 + gy) * 64 + ox] = __uint_as_float(hi);
    }
}

// =================== launch ===================
extern "C" void kernel_launch(void* const* d_in, const int* in_sizes, int n_in,
                              void* d_out, int out_size) {
    const float* images = (const float*)d_in[0];
    const float* actions = (const float*)d_in[1];
    const float* pe_w1 = (const float*)d_in[2];
    const float* pe_b1 = (const float*)d_in[3];
    const float* pe_w2 = (const float*)d_in[4];
    const float* pe_b2 = (const float*)d_in[5];
    const float* ae_w1 = (const float*)d_in[6];
    const float* ae_b1 = (const float*)d_in[7];
    const float* ae_w2 = (const float*)d_in[8];
    const float* ae_b2 = (const float*)d_in[9];
    const float* mp_w1 = (const float*)d_in[10];
    const float* mp_b1 = (const float*)d_in[11];
    const float* mp_w2 = (const float*)d_in[12];
    const float* mp_b2 = (const float*)d_in[13];
    float* out = (float*)d_out;

    cudaFuncSetAttribute(conv2_kernel,
                         cudaFuncAttributeMaxDynamicSharedMemorySize, C2_SMEM);

    ae_kernel<<<NB, 256>>>(actions, ae_w1, ae_b1, ae_w2, ae_b2);
    conv1_kernel<<<dim3(4, 8, NB), 256>>>(images, pe_w1, pe_b1);
    conv2_kernel<<<dim3(2, 4, NB), 256, C2_SMEM>>>(pe_w2, pe_b2);
    xconv_kernel<<<dim3(32, NB), 256>>>();
    mp1_kernel<<<dim3(2, 4, NB), 256>>>(mp_w1, mp_b1);
    mp2_kernel<<<dim3(1, 4, NB), 256>>>(mp_w2, mp_b2, out);
}

// round 13
// speedup vs baseline: 1.0089x; 1.0089x over previous
#include <cuda_runtime.h>
#include <cuda_bf16.h>
#include <cstdint>

#define NB 64
#define CC 32
#define KK 5
#define ADIM 4
#define AHID 256

typedef unsigned long long u64;

// packed f32x2 helpers
#define PACK2(out, lo, hi) \
    asm("mov.b64 %0, {%1, %2};" : "=l"(out) : "r"(lo), "r"(hi))
#define FMA2(acc, a, b) \
    asm("fma.rn.f32x2 %0, %1, %2, %0;" : "+l"(acc) : "l"(a), "l"(b))
#define UNPACK2(lo, hi, in) \
    asm("mov.b64 {%0, %1}, %2;" : "=r"(lo), "=r"(hi) : "l"(in))

__device__ __forceinline__ u64 pack_dup(float v) {
    u64 r; unsigned u = __float_as_uint(v);
    PACK2(r, u, u); return r;
}

// ---------------- scratch ----------------
__device__ float g_h1[NB * CC * 128 * 128];
__device__ float g_h2[NB * CC * 64 * 64];
__device__ float g_ker[NB * CC * KK * KK];
__device__ float g_sa[NB * CC * 64 * 64];
__device__ float g_f [NB * CC * 64 * 64];

// =================== action encoder MLP ===================
__global__ void ae_kernel(const float* __restrict__ act,
                          const float* __restrict__ w1, const float* __restrict__ b1,
                          const float* __restrict__ w2, const float* __restrict__ b2) {
    __shared__ float sH[AHID];
    __shared__ float sA[ADIM];
    int n = blockIdx.x, tid = threadIdx.x;
    if (tid < ADIM) sA[tid] = act[n * ADIM + tid];
    __syncthreads();
    float h = b1[tid];
#pragma unroll
    for (int i = 0; i < ADIM; i++) h = fmaf(sA[i], w1[i * AHID + tid], h);
    sH[tid] = fmaxf(h, 0.f);
    __syncthreads();
    for (int o = tid; o < CC * KK * KK; o += 256) {
        float acc = b2[o];
#pragma unroll 8
        for (int j = 0; j < AHID; j++) acc = fmaf(sH[j], w2[j * (CC * KK * KK) + o], acc);
        g_ker[n * (CC * KK * KK) + o] = acc;
    }
}

// =================== conv1: 3->32, k5, s2, p2, NHWC in ===================
__global__ void __launch_bounds__(256, 2)
conv1_kernel(const float* __restrict__ img,
             const float* __restrict__ w, const float* __restrict__ b) {
    __shared__ __align__(16) float sIn[2][3 * 35 * 34];
    __shared__ __align__(16) float sW[75 * 32];
    __shared__ __align__(8) float sB[32];
    int n = blockIdx.z;
    int ox0 = blockIdx.x * 32, oy0 = blockIdx.y * 16;
    int tid = threadIdx.x;

    for (int i = tid; i < 75 * 32; i += 256) {
        int o = i & 31, tap = i >> 5;
        int c = tap / 25, r = tap % 25, kh = r / 5, kw = r % 5;
        sW[i] = w[((o * 3 + c) * 5 + kh) * 5 + kw];
    }
    if (tid < 32) sB[tid] = b[tid];

    int iy0 = oy0 * 2 - 2, ix0 = ox0 * 2 - 2;
    for (int i = tid; i < 3 * 35 * 67; i += 256) {
        int c = i / (35 * 67), r = i % (35 * 67);
        int iy = r / 67, ix = r % 67;
        int gy = iy0 + iy, gx = ix0 + ix;
        float v = 0.f;
        if ((unsigned)gy < 256u && (unsigned)gx < 256u)
            v = img[((n * 256 + gy) * 256 + gx) * 3 + c];
        sIn[ix & 1][c * 1190 + iy * 34 + (ix >> 1)] = v;
    }
    __syncthreads();

    int ox = tid & 31, oyr = tid >> 5;
    u64 accA[16], accB[16];
    const u64* sB2 = (const u64*)sB;
#pragma unroll
    for (int o = 0; o < 16; o++) { accA[o] = sB2[o]; accB[o] = sB2[o]; }

    for (int c = 0; c < 3; c++)
        for (int kh = 0; kh < 5; kh++) {
            int base = c * 1190 + (2 * oyr + kh) * 34 + ox;
            const float* pl[2] = { &sIn[0][base], &sIn[1][base] };
#pragma unroll
            for (int kw = 0; kw < 5; kw++) {
                float fA = pl[kw & 1][kw >> 1];
                float fB = pl[kw & 1][(kw >> 1) + 544];
                u64 vA2 = pack_dup(fA);
                u64 vB2 = pack_dup(fB);
                const ulonglong2* wq =
                    (const ulonglong2*)&sW[((c * 5 + kh) * 5 + kw) * 32];
#pragma unroll
                for (int o2 = 0; o2 < 8; o2++) {
                    ulonglong2 ww = wq[o2];
                    FMA2(accA[2 * o2], vA2, ww.x);
                    FMA2(accA[2 * o2 + 1], vA2, ww.y);
                    FMA2(accB[2 * o2], vB2, ww.x);
                    FMA2(accB[2 * o2 + 1], vB2, ww.y);
                }
            }
        }

    int gyA = oy0 + oyr, gyB = gyA + 8, gx = ox0 + ox;
#pragma unroll
    for (int o = 0; o < 16; o++) {
        unsigned lo, hi;
        UNPACK2(lo, hi, accA[o]);
        g_h1[((n * 32 + 2 * o) * 128 + gyA) * 128 + gx] = fmaxf(__uint_as_float(lo), 0.f);
        g_h1[((n * 32 + 2 * o + 1) * 128 + gyA) * 128 + gx] = fmaxf(__uint_as_float(hi), 0.f);
        UNPACK2(lo, hi, accB[o]);
        g_h1[((n * 32 + 2 * o) * 128 + gyB) * 128 + gx] = fmaxf(__uint_as_float(lo), 0.f);
        g_h1[((n * 32 + 2 * o + 1) * 128 + gyB) * 128 + gx] = fmaxf(__uint_as_float(hi), 0.f);
    }
}

// =================== conv2: 32->32, k5, s2, p2 ===================
__global__ void __launch_bounds__(256, 2)
conv2_kernel(const float* __restrict__ w, const float* __restrict__ b) {
    __shared__ __align__(16) float sIn[2][2][1190];
    __shared__ __align__(16) float sW[2][800];
    __shared__ __align__(8) float sB[32];
    int n = blockIdx.z;
    int ox0 = blockIdx.x * 32, oy0 = blockIdx.y * 16;
    int tid = threadIdx.x;
    int ox = tid & 31, oyr = tid >> 5;
    if (tid < 32) sB[tid] = b[tid];

    int iy0 = oy0 * 2 - 2, ix0 = ox0 * 2 - 2;

    float pin[10], pw[4];
    {
        const float* src = &g_h1[(n * 32 + 0) * 16384];
#pragma unroll
        for (int j = 0; j < 10; j++) {
            int i = tid + j * 256; float v = 0.f;
            if (i < 2345) {
                int iy = i / 67, ix = i % 67;
                int gy = iy0 + iy, gx = ix0 + ix;
                if ((unsigned)gy < 128u && (unsigned)gx < 128u) v = src[gy * 128 + gx];
            }
            pin[j] = v;
        }
#pragma unroll
        for (int j = 0; j < 4; j++) {
            int i = tid + j * 256; float v = 0.f;
            if (i < 800) { int o = i & 31, tap = i >> 5; v = w[(o * 32 + 0) * 25 + tap]; }
            pw[j] = v;
        }
    }
#pragma unroll
    for (int j = 0; j < 10; j++) {
        int i = tid + j * 256;
        if (i < 2345) {
            int iy = i / 67, ix = i % 67;
            sIn[0][ix & 1][iy * 34 + (ix >> 1)] = pin[j];
        }
    }
#pragma unroll
    for (int j = 0; j < 4; j++) { int i = tid + j * 256; if (i < 800) sW[0][i] = pw[j]; }
    __syncthreads();

    u64 accA[16], accB[16];
    const u64* sB2 = (const u64*)sB;
#pragma unroll
    for (int o = 0; o < 16; o++) { accA[o] = sB2[o]; accB[o] = sB2[o]; }

    for (int ic = 0; ic < 32; ic++) {
        int cur = ic & 1;
        if (ic < 31) {
            const float* src = &g_h1[(n * 32 + ic + 1) * 16384];
#pragma unroll
            for (int j = 0; j < 10; j++) {
                int i = tid + j * 256; float v = 0.f;
                if (i < 2345) {
                    int iy = i / 67, ix = i % 67;
                    int gy = iy0 + iy, gx = ix0 + ix;
                    if ((unsigned)gy < 128u && (unsigned)gx < 128u) v = src[gy * 128 + gx];
                }
                pin[j] = v;
            }
#pragma unroll
            for (int j = 0; j < 4; j++) {
                int i = tid + j * 256; float v = 0.f;
                if (i < 800) { int o = i & 31, tap = i >> 5; v = w[(o * 32 + ic + 1) * 25 + tap]; }
                pw[j] = v;
            }
        }
#pragma unroll
        for (int kh = 0; kh < 5; kh++) {
            int base = (2 * oyr + kh) * 34 + ox;
            const float* pl[2] = { &sIn[cur][0][base], &sIn[cur][1][base] };
#pragma unroll
            for (int kw = 0; kw < 5; kw++) {
                float fA = pl[kw & 1][kw >> 1];
                float fB = pl[kw & 1][(kw >> 1) + 544];
                u64 vA2 = pack_dup(fA);
                u64 vB2 = pack_dup(fB);
                const ulonglong2* wq = (const ulonglong2*)&sW[cur][(kh * 5 + kw) * 32];
#pragma unroll
                for (int o2 = 0; o2 < 8; o2++) {
                    ulonglong2 ww = wq[o2];
                    FMA2(accA[2 * o2], vA2, ww.x);
                    FMA2(accA[2 * o2 + 1], vA2, ww.y);
                    FMA2(accB[2 * o2], vB2, ww.x);
                    FMA2(accB[2 * o2 + 1], vB2, ww.y);
                }
            }
        }
        if (ic < 31) {
#pragma unroll
            for (int j = 0; j < 10; j++) {
                int i = tid + j * 256;
                if (i < 2345) {
                    int iy = i / 67, ix = i % 67;
                    sIn[1 - cur][ix & 1][iy * 34 + (ix >> 1)] = pin[j];
                }
            }
#pragma unroll
            for (int j = 0; j < 4; j++) { int i = tid + j * 256; if (i < 800) sW[1 - cur][i] = pw[j]; }
        }
        __syncthreads();
    }

    int gyA = oy0 + oyr, gyB = gyA + 8, gx = ox0 + ox;
#pragma unroll
    for (int o = 0; o < 16; o++) {
        unsigned lo, hi;
        UNPACK2(lo, hi, accA[o]);
        g_h2[((n * 32 + 2 * o) * 64 + gyA) * 64 + gx] = fmaxf(__uint_as_float(lo), 0.f);
        g_h2[((n * 32 + 2 * o + 1) * 64 + gyA) * 64 + gx] = fmaxf(__uint_as_float(hi), 0.f);
        UNPACK2(lo, hi, accB[o]);
        g_h2[((n * 32 + 2 * o) * 64 + gyB) * 64 + gx] = fmaxf(__uint_as_float(lo), 0.f);
        g_h2[((n * 32 + 2 * o + 1) * 64 + gyB) * 64 + gx] = fmaxf(__uint_as_float(hi), 0.f);
    }
}

// =================== cross-conv: depthwise k5 p2 — CHANNEL-PAIR FMA2 ===================
// One block = one (n, channel-pair). Inputs packed {c2p, c2p+1} as u64 planes,
// kernels packed per tap; identical row-reuse loop now does 2 channels/instr.
#define XC_SMEM (68 * 68 * 8)
__global__ void __launch_bounds__(256)
xconv_kernel() {
    extern __shared__ __align__(16) u64 xsm[];   // 68x68 packed pair plane
    __shared__ __align__(8) float sK[50];        // interleaved {k0[t], k1[t]}
    int p = blockIdx.x;    // channel pair 0..15
    int n = blockIdx.y;
    int tid = threadIdx.x;
    const float* src0 = &g_h2[((size_t)n * 32 + 2 * p) * 4096];
    const float* src1 = src0 + 4096;
    for (int i = tid; i < 68 * 68; i += 256) {
        int iy = i / 68, ix = i % 68;
        int gy = iy - 2, gx = ix - 2;
        float a = 0.f, bb = 0.f;
        if ((unsigned)gy < 64u && (unsigned)gx < 64u) {
            a = src0[gy * 64 + gx];
            bb = src1[gy * 64 + gx];
        }
        u64 v; PACK2(v, __float_as_uint(a), __float_as_uint(bb));
        xsm[i] = v;
    }
    if (tid < 50)
        sK[tid] = g_ker[((size_t)n * 32 + 2 * p + (tid & 1)) * 25 + (tid >> 1)];
    __syncthreads();

    u64 k2[25];
    const u64* sK2 = (const u64*)sK;
#pragma unroll
    for (int t = 0; t < 25; t++) k2[t] = sK2[t];

    int tx = tid & 63, ty = tid >> 6;
    int ybase = ty * 16;
    u64 acc[16];
#pragma unroll
    for (int j = 0; j < 16; j++) acc[j] = 0ull;

#pragma unroll
    for (int iy = 0; iy < 20; iy++) {
        const u64* row = &xsm[(ybase + iy) * 68 + tx];
        u64 v0 = row[0], v1 = row[1], v2 = row[2], v3 = row[3], v4 = row[4];
#pragma unroll
        for (int kh = 0; kh < 5; kh++) {
            int j = iy - kh;
            if (j >= 0 && j < 16) {
                FMA2(acc[j], v0, k2[kh * 5 + 0]);
                FMA2(acc[j], v1, k2[kh * 5 + 1]);
                FMA2(acc[j], v2, k2[kh * 5 + 2]);
                FMA2(acc[j], v3, k2[kh * 5 + 3]);
                FMA2(acc[j], v4, k2[kh * 5 + 4]);
            }
        }
    }
    float* dst0 = &g_sa[((size_t)n * 32 + 2 * p) * 4096 + tx];
    float* dst1 = dst0 + 4096;
#pragma unroll
    for (int j = 0; j < 16; j++) {
        unsigned lo, hi;
        UNPACK2(lo, hi, acc[j]);
        dst0[(ybase + j) * 64] = __uint_as_float(lo);
        dst1[(ybase + j) * 64] = __uint_as_float(hi);
    }
}

// =================== mp1: 32->32, k3, p1, relu ===================
__global__ void __launch_bounds__(256, 2)
mp1_kernel(const float* __restrict__ w, const float* __restrict__ b) {
    __shared__ __align__(16) float sIn[2][18 * 34];
    __shared__ __align__(16) float sW[2][288];
    __shared__ __align__(8) float sB[32];
    int n = blockIdx.z;
    int ox0 = blockIdx.x * 32, oy0 = blockIdx.y * 16;
    int tid = threadIdx.x;
    int ox = tid & 31, oyr = tid >> 5;
    if (tid < 32) sB[tid] = b[tid];

    int iy0 = oy0 - 1, ix0 = ox0 - 1;

    float pin[3], pw[2];
    {
        const float* src = &g_sa[(n * 32 + 0) * 4096];
#pragma unroll
        for (int j = 0; j < 3; j++) {
            int i = tid + j * 256; float v = 0.f;
            if (i < 612) {
                int iy = i / 34, ix = i % 34;
                int gy = iy0 + iy, gx = ix0 + ix;
                if ((unsigned)gy < 64u && (unsigned)gx < 64u) v = src[gy * 64 + gx];
            }
            pin[j] = v;
        }
#pragma unroll
        for (int j = 0; j < 2; j++) {
            int i = tid + j * 256; float v = 0.f;
            if (i < 288) { int o = i & 31, tap = i >> 5; v = w[(o * 32 + 0) * 9 + tap]; }
            pw[j] = v;
        }
    }
#pragma unroll
    for (int j = 0; j < 3; j++) { int i = tid + j * 256; if (i < 612) sIn[0][i] = pin[j]; }
#pragma unroll
    for (int j = 0; j < 2; j++) { int i = tid + j * 256; if (i < 288) sW[0][i] = pw[j]; }
    __syncthreads();

    u64 accA[16], accB[16];
    const u64* sB2 = (const u64*)sB;
#pragma unroll
    for (int o = 0; o < 16; o++) { accA[o] = sB2[o]; accB[o] = sB2[o]; }

    for (int ic = 0; ic < 32; ic++) {
        int cur = ic & 1;
        if (ic < 31) {
            const float* src = &g_sa[(n * 32 + ic + 1) * 4096];
#pragma unroll
            for (int j = 0; j < 3; j++) {
                int i = tid + j * 256; float v = 0.f;
                if (i < 612) {
                    int iy = i / 34, ix = i % 34;
                    int gy = iy0 + iy, gx = ix0 + ix;
                    if ((unsigned)gy < 64u && (unsigned)gx < 64u) v = src[gy * 64 + gx];
                }
                pin[j] = v;
            }
#pragma unroll
            for (int j = 0; j < 2; j++) {
                int i = tid + j * 256; float v = 0.f;
                if (i < 288) { int o = i & 31, tap = i >> 5; v = w[(o * 32 + ic + 1) * 9 + tap]; }
                pw[j] = v;
            }
        }
#pragma unroll
        for (int kh = 0; kh < 3; kh++) {
            const float* rA = &sIn[cur][(oyr + kh) * 34 + ox];
            const float* rB = rA + 8 * 34;
#pragma unroll
            for (int kw = 0; kw < 3; kw++) {
                u64 vA2 = pack_dup(rA[kw]);
                u64 vB2 = pack_dup(rB[kw]);
                const ulonglong2* wq = (const ulonglong2*)&sW[cur][(kh * 3 + kw) * 32];
#pragma unroll
                for (int o2 = 0; o2 < 8; o2++) {
                    ulonglong2 ww = wq[o2];
                    FMA2(accA[2 * o2], vA2, ww.x);
                    FMA2(accA[2 * o2 + 1], vA2, ww.y);
                    FMA2(accB[2 * o2], vB2, ww.x);
                    FMA2(accB[2 * o2 + 1], vB2, ww.y);
                }
            }
        }
        if (ic < 31) {
#pragma unroll
            for (int j = 0; j < 3; j++) { int i = tid + j * 256; if (i < 612) sIn[1 - cur][i] = pin[j]; }
#pragma unroll
            for (int j = 0; j < 2; j++) { int i = tid + j * 256; if (i < 288) sW[1 - cur][i] = pw[j]; }
        }
        __syncthreads();
    }

    int gyA = oy0 + oyr, gyB = gyA + 8, gx = ox0 + ox;
#pragma unroll
    for (int o = 0; o < 16; o++) {
        unsigned lo, hi;
        UNPACK2(lo, hi, accA[o]);
        g_f[((n * 32 + 2 * o) * 64 + gyA) * 64 + gx] = fmaxf(__uint_as_float(lo), 0.f);
        g_f[((n * 32 + 2 * o + 1) * 64 + gyA) * 64 + gx] = fmaxf(__uint_as_float(hi), 0.f);
        UNPACK2(lo, hi, accB[o]);
        g_f[((n * 32 + 2 * o) * 64 + gyB) * 64 + gx] = fmaxf(__uint_as_float(lo), 0.f);
        g_f[((n * 32 + 2 * o + 1) * 64 + gyB) * 64 + gx] = fmaxf(__uint_as_float(hi), 0.f);
    }
}

// =================== mp2: 32->2, k3, p1 (2 px/thread) ===================
__global__ void __launch_bounds__(256, 2)
mp2_kernel(const float* __restrict__ w, const float* __restrict__ b,
           float* __restrict__ out) {
    __shared__ __align__(8) float sIn[2][18 * 34];
    __shared__ __align__(8) float sW[2][18];
    int n = blockIdx.z;
    int ox0 = blockIdx.x * 32, oy0 = blockIdx.y * 16;
    int tid = threadIdx.x;
    int ox = tid & 31, oyr = tid >> 5;

    int iy0 = oy0 - 1, ix0 = ox0 - 1;

    float pin[3], pwv;
    {
        const float* src = &g_f[(n * 32 + 0) * 4096];
#pragma unroll
        for (int j = 0; j < 3; j++) {
            int i = tid + j * 256; float v = 0.f;
            if (i < 612) {
                int iy = i / 34, ix = i % 34;
                int gy = iy0 + iy, gx = ix0 + ix;
                if ((unsigned)gy < 64u && (unsigned)gx < 64u) v = src[gy * 64 + gx];
            }
            pin[j] = v;
        }
        pwv = (tid < 18) ? w[((tid & 1) * 32 + 0) * 9 + (tid >> 1)] : 0.f;
    }
#pragma unroll
    for (int j = 0; j < 3; j++) { int i = tid + j * 256; if (i < 612) sIn[0][i] = pin[j]; }
    if (tid < 18) sW[0][tid] = pwv;
    __syncthreads();

    u64 accA2, accB2;
    PACK2(accA2, __float_as_uint(b[0]), __float_as_uint(b[1]));
    accB2 = accA2;

    for (int ic = 0; ic < 32; ic++) {
        int cur = ic & 1;
        if (ic < 31) {
            const float* src = &g_f[(n * 32 + ic + 1) * 4096];
#pragma unroll
            for (int j = 0; j < 3; j++) {
                int i = tid + j * 256; float v = 0.f;
                if (i < 612) {
                    int iy = i / 34, ix = i % 34;
                    int gy = iy0 + iy, gx = ix0 + ix;
                    if ((unsigned)gy < 64u && (unsigned)gx < 64u) v = src[gy * 64 + gx];
                }
                pin[j] = v;
            }
            pwv = (tid < 18) ? w[((tid & 1) * 32 + ic + 1) * 9 + (tid >> 1)] : 0.f;
        }
        const u64* wp2 = (const u64*)&sW[cur][0];
#pragma unroll
        for (int kh = 0; kh < 3; kh++) {
            const float* rA = &sIn[cur][(oyr + kh) * 34 + ox];
            const float* rB = rA + 8 * 34;
#pragma unroll
            for (int kw = 0; kw < 3; kw++) {
                u64 w2 = wp2[kh * 3 + kw];
                FMA2(accA2, pack_dup(rA[kw]), w2);
                FMA2(accB2, pack_dup(rB[kw]), w2);
            }
        }
        if (ic < 31) {
#pragma unroll
            for (int j = 0; j < 3; j++) { int i = tid + j * 256; if (i < 612) sIn[1 - cur][i] = pin[j]; }
            if (tid < 18) sW[1 - cur][tid] = pwv;
        }
        __syncthreads();
    }
    int gyA = oy0 + oyr, gyB = gyA + 8, gx = ox0 + ox;
    unsigned lo, hi;
    UNPACK2(lo, hi, accA2);
    out[((n * 2 + 0) * 64 + gyA) * 64 + gx] = __uint_as_float(lo);
    out[((n * 2 + 1) * 64 + gyA) * 64 + gx] = __uint_as_float(hi);
    UNPACK2(lo, hi, accB2);
    out[((n * 2 + 0) * 64 + gyB) * 64 + gx] = __uint_as_float(lo);
    out[((n * 2 + 1) * 64 + gyB) * 64 + gx] = __uint_as_float(hi);
}

// =================== launch ===================
extern "C" void kernel_launch(void* const* d_in, const int* in_sizes, int n_in,
                              void* d_out, int out_size) {
    const float* images = (const float*)d_in[0];
    const float* actions = (const float*)d_in[1];
    const float* pe_w1 = (const float*)d_in[2];
    const float* pe_b1 = (const float*)d_in[3];
    const float* pe_w2 = (const float*)d_in[4];
    const float* pe_b2 = (const float*)d_in[5];
    const float* ae_w1 = (const float*)d_in[6];
    const float* ae_b1 = (const float*)d_in[7];
    const float* ae_w2 = (const float*)d_in[8];
    const float* ae_b2 = (const float*)d_in[9];
    const float* mp_w1 = (const float*)d_in[10];
    const float* mp_b1 = (const float*)d_in[11];
    const float* mp_w2 = (const float*)d_in[12];
    const float* mp_b2 = (const float*)d_in[13];
    float* out = (float*)d_out;

    ae_kernel<<<NB, 256>>>(actions, ae_w1, ae_b1, ae_w2, ae_b2);
    conv1_kernel<<<dim3(4, 8, NB), 256>>>(images, pe_w1, pe_b1);
    conv2_kernel<<<dim3(2, 4, NB), 256>>>(pe_w2, pe_b2);
    xconv_kernel<<<dim3(16, NB), 256, XC_SMEM>>>();
    mp1_kernel<<<dim3(2, 4, NB), 256>>>(mp_w1, mp_b1);
    mp2_kernel<<<dim3(2, 4, NB), 256>>>(mp_w2, mp_b2, out);
}

// round 14
// speedup vs baseline: 1.0132x; 1.0043x over previous
#include <cuda_runtime.h>
#include <cuda_bf16.h>
#include <cstdint>

#define NB 64
#define CC 32
#define KK 5
#define ADIM 4
#define AHID 256

typedef unsigned long long u64;

// packed f32x2 helpers
#define PACK2(out, lo, hi) \
    asm("mov.b64 %0, {%1, %2};" : "=l"(out) : "r"(lo), "r"(hi))
#define FMA2(acc, a, b) \
    asm("fma.rn.f32x2 %0, %1, %2, %0;" : "+l"(acc) : "l"(a), "l"(b))
#define UNPACK2(lo, hi, in) \
    asm("mov.b64 {%0, %1}, %2;" : "=r"(lo), "=r"(hi) : "l"(in))

__device__ __forceinline__ u64 pack_dup(float v) {
    u64 r; unsigned u = __float_as_uint(v);
    PACK2(r, u, u); return r;
}

// ---------------- scratch ----------------
__device__ float g_h1[NB * CC * 128 * 128];
__device__ float g_h2[NB * CC * 64 * 64];
__device__ float g_ker[NB * CC * KK * KK];
__device__ float g_sa[NB * CC * 64 * 64];
__device__ float g_f [NB * CC * 64 * 64];

// =================== action encoder MLP ===================
__global__ void ae_kernel(const float* __restrict__ act,
                          const float* __restrict__ w1, const float* __restrict__ b1,
                          const float* __restrict__ w2, const float* __restrict__ b2) {
    __shared__ float sH[AHID];
    __shared__ float sA[ADIM];
    int n = blockIdx.x, tid = threadIdx.x;
    if (tid < ADIM) sA[tid] = act[n * ADIM + tid];
    __syncthreads();
    float h = b1[tid];
#pragma unroll
    for (int i = 0; i < ADIM; i++) h = fmaf(sA[i], w1[i * AHID + tid], h);
    sH[tid] = fmaxf(h, 0.f);
    __syncthreads();
    for (int o = tid; o < CC * KK * KK; o += 256) {
        float acc = b2[o];
#pragma unroll 8
        for (int j = 0; j < AHID; j++) acc = fmaf(sH[j], w2[j * (CC * KK * KK) + o], acc);
        g_ker[n * (CC * KK * KK) + o] = acc;
    }
}

// =================== conv1: 3->32, k5, s2, p2, NHWC in ===================
__global__ void __launch_bounds__(256, 2)
conv1_kernel(const float* __restrict__ img,
             const float* __restrict__ w, const float* __restrict__ b) {
    __shared__ __align__(16) float sIn[2][3 * 35 * 34];
    __shared__ __align__(16) float sW[75 * 32];
    __shared__ __align__(8) float sB[32];
    int n = blockIdx.z;
    int ox0 = blockIdx.x * 32, oy0 = blockIdx.y * 16;
    int tid = threadIdx.x;

    for (int i = tid; i < 75 * 32; i += 256) {
        int o = i & 31, tap = i >> 5;
        int c = tap / 25, r = tap % 25, kh = r / 5, kw = r % 5;
        sW[i] = w[((o * 3 + c) * 5 + kh) * 5 + kw];
    }
    if (tid < 32) sB[tid] = b[tid];

    int iy0 = oy0 * 2 - 2, ix0 = ox0 * 2 - 2;
    for (int i = tid; i < 3 * 35 * 67; i += 256) {
        int c = i / (35 * 67), r = i % (35 * 67);
        int iy = r / 67, ix = r % 67;
        int gy = iy0 + iy, gx = ix0 + ix;
        float v = 0.f;
        if ((unsigned)gy < 256u && (unsigned)gx < 256u)
            v = img[((n * 256 + gy) * 256 + gx) * 3 + c];
        sIn[ix & 1][c * 1190 + iy * 34 + (ix >> 1)] = v;
    }
    __syncthreads();

    int ox = tid & 31, oyr = tid >> 5;
    u64 accA[16], accB[16];
    const u64* sB2 = (const u64*)sB;
#pragma unroll
    for (int o = 0; o < 16; o++) { accA[o] = sB2[o]; accB[o] = sB2[o]; }

    for (int c = 0; c < 3; c++)
        for (int kh = 0; kh < 5; kh++) {
            int base = c * 1190 + (2 * oyr + kh) * 34 + ox;
            const float* pl[2] = { &sIn[0][base], &sIn[1][base] };
#pragma unroll
            for (int kw = 0; kw < 5; kw++) {
                float fA = pl[kw & 1][kw >> 1];
                float fB = pl[kw & 1][(kw >> 1) + 544];
                u64 vA2 = pack_dup(fA);
                u64 vB2 = pack_dup(fB);
                const ulonglong2* wq =
                    (const ulonglong2*)&sW[((c * 5 + kh) * 5 + kw) * 32];
#pragma unroll
                for (int o2 = 0; o2 < 8; o2++) {
                    ulonglong2 ww = wq[o2];
                    FMA2(accA[2 * o2], vA2, ww.x);
                    FMA2(accA[2 * o2 + 1], vA2, ww.y);
                    FMA2(accB[2 * o2], vB2, ww.x);
                    FMA2(accB[2 * o2 + 1], vB2, ww.y);
                }
            }
        }

    int gyA = oy0 + oyr, gyB = gyA + 8, gx = ox0 + ox;
#pragma unroll
    for (int o = 0; o < 16; o++) {
        unsigned lo, hi;
        UNPACK2(lo, hi, accA[o]);
        g_h1[((n * 32 + 2 * o) * 128 + gyA) * 128 + gx] = fmaxf(__uint_as_float(lo), 0.f);
        g_h1[((n * 32 + 2 * o + 1) * 128 + gyA) * 128 + gx] = fmaxf(__uint_as_float(hi), 0.f);
        UNPACK2(lo, hi, accB[o]);
        g_h1[((n * 32 + 2 * o) * 128 + gyB) * 128 + gx] = fmaxf(__uint_as_float(lo), 0.f);
        g_h1[((n * 32 + 2 * o + 1) * 128 + gyB) * 128 + gx] = fmaxf(__uint_as_float(hi), 0.f);
    }
}

// =================== conv2: 32->32, k5, s2, p2 ===================
__global__ void __launch_bounds__(256, 2)
conv2_kernel(const float* __restrict__ w, const float* __restrict__ b) {
    __shared__ __align__(16) float sIn[2][2][1190];
    __shared__ __align__(16) float sW[2][800];
    __shared__ __align__(8) float sB[32];
    int n = blockIdx.z;
    int ox0 = blockIdx.x * 32, oy0 = blockIdx.y * 16;
    int tid = threadIdx.x;
    int ox = tid & 31, oyr = tid >> 5;
    if (tid < 32) sB[tid] = b[tid];

    int iy0 = oy0 * 2 - 2, ix0 = ox0 * 2 - 2;

    float pin[10], pw[4];
    {
        const float* src = &g_h1[(n * 32 + 0) * 16384];
#pragma unroll
        for (int j = 0; j < 10; j++) {
            int i = tid + j * 256; float v = 0.f;
            if (i < 2345) {
                int iy = i / 67, ix = i % 67;
                int gy = iy0 + iy, gx = ix0 + ix;
                if ((unsigned)gy < 128u && (unsigned)gx < 128u) v = src[gy * 128 + gx];
            }
            pin[j] = v;
        }
#pragma unroll
        for (int j = 0; j < 4; j++) {
            int i = tid + j * 256; float v = 0.f;
            if (i < 800) { int o = i & 31, tap = i >> 5; v = w[(o * 32 + 0) * 25 + tap]; }
            pw[j] = v;
        }
    }
#pragma unroll
    for (int j = 0; j < 10; j++) {
        int i = tid + j * 256;
        if (i < 2345) {
            int iy = i / 67, ix = i % 67;
            sIn[0][ix & 1][iy * 34 + (ix >> 1)] = pin[j];
        }
    }
#pragma unroll
    for (int j = 0; j < 4; j++) { int i = tid + j * 256; if (i < 800) sW[0][i] = pw[j]; }
    __syncthreads();

    u64 accA[16], accB[16];
    const u64* sB2 = (const u64*)sB;
#pragma unroll
    for (int o = 0; o < 16; o++) { accA[o] = sB2[o]; accB[o] = sB2[o]; }

    for (int ic = 0; ic < 32; ic++) {
        int cur = ic & 1;
        if (ic < 31) {
            const float* src = &g_h1[(n * 32 + ic + 1) * 16384];
#pragma unroll
            for (int j = 0; j < 10; j++) {
                int i = tid + j * 256; float v = 0.f;
                if (i < 2345) {
                    int iy = i / 67, ix = i % 67;
                    int gy = iy0 + iy, gx = ix0 + ix;
                    if ((unsigned)gy < 128u && (unsigned)gx < 128u) v = src[gy * 128 + gx];
                }
                pin[j] = v;
            }
#pragma unroll
            for (int j = 0; j < 4; j++) {
                int i = tid + j * 256; float v = 0.f;
                if (i < 800) { int o = i & 31, tap = i >> 5; v = w[(o * 32 + ic + 1) * 25 + tap]; }
                pw[j] = v;
            }
        }
#pragma unroll
        for (int kh = 0; kh < 5; kh++) {
            int base = (2 * oyr + kh) * 34 + ox;
            const float* pl[2] = { &sIn[cur][0][base], &sIn[cur][1][base] };
#pragma unroll
            for (int kw = 0; kw < 5; kw++) {
                float fA = pl[kw & 1][kw >> 1];
                float fB = pl[kw & 1][(kw >> 1) + 544];
                u64 vA2 = pack_dup(fA);
                u64 vB2 = pack_dup(fB);
                const ulonglong2* wq = (const ulonglong2*)&sW[cur][(kh * 5 + kw) * 32];
#pragma unroll
                for (int o2 = 0; o2 < 8; o2++) {
                    ulonglong2 ww = wq[o2];
                    FMA2(accA[2 * o2], vA2, ww.x);
                    FMA2(accA[2 * o2 + 1], vA2, ww.y);
                    FMA2(accB[2 * o2], vB2, ww.x);
                    FMA2(accB[2 * o2 + 1], vB2, ww.y);
                }
            }
        }
        if (ic < 31) {
#pragma unroll
            for (int j = 0; j < 10; j++) {
                int i = tid + j * 256;
                if (i < 2345) {
                    int iy = i / 67, ix = i % 67;
                    sIn[1 - cur][ix & 1][iy * 34 + (ix >> 1)] = pin[j];
                }
            }
#pragma unroll
            for (int j = 0; j < 4; j++) { int i = tid + j * 256; if (i < 800) sW[1 - cur][i] = pw[j]; }
        }
        __syncthreads();
    }

    int gyA = oy0 + oyr, gyB = gyA + 8, gx = ox0 + ox;
#pragma unroll
    for (int o = 0; o < 16; o++) {
        unsigned lo, hi;
        UNPACK2(lo, hi, accA[o]);
        g_h2[((n * 32 + 2 * o) * 64 + gyA) * 64 + gx] = fmaxf(__uint_as_float(lo), 0.f);
        g_h2[((n * 32 + 2 * o + 1) * 64 + gyA) * 64 + gx] = fmaxf(__uint_as_float(hi), 0.f);
        UNPACK2(lo, hi, accB[o]);
        g_h2[((n * 32 + 2 * o) * 64 + gyB) * 64 + gx] = fmaxf(__uint_as_float(lo), 0.f);
        g_h2[((n * 32 + 2 * o + 1) * 64 + gyB) * 64 + gx] = fmaxf(__uint_as_float(hi), 0.f);
    }
}

// =================== cross-conv: depthwise k5 p2 — channel-pair FMA2, 512 thr ===================
// One block = one (n, channel-pair); 512 threads, each owns an 8-row column.
#define XC_SMEM (68 * 68 * 8)
__global__ void __launch_bounds__(512)
xconv_kernel() {
    extern __shared__ __align__(16) u64 xsm[];   // 68x68 packed pair plane
    __shared__ __align__(8) float sK[50];        // interleaved {k0[t], k1[t]}
    int p = blockIdx.x;    // channel pair 0..15
    int n = blockIdx.y;
    int tid = threadIdx.x;
    const float* src0 = &g_h2[((size_t)n * 32 + 2 * p) * 4096];
    const float* src1 = src0 + 4096;
    for (int i = tid; i < 68 * 68; i += 512) {
        int iy = i / 68, ix = i % 68;
        int gy = iy - 2, gx = ix - 2;
        float a = 0.f, bb = 0.f;
        if ((unsigned)gy < 64u && (unsigned)gx < 64u) {
            a = src0[gy * 64 + gx];
            bb = src1[gy * 64 + gx];
        }
        u64 v; PACK2(v, __float_as_uint(a), __float_as_uint(bb));
        xsm[i] = v;
    }
    if (tid < 50)
        sK[tid] = g_ker[((size_t)n * 32 + 2 * p + (tid & 1)) * 25 + (tid >> 1)];
    __syncthreads();

    u64 k2[25];
    const u64* sK2 = (const u64*)sK;
#pragma unroll
    for (int t = 0; t < 25; t++) k2[t] = sK2[t];

    int tx = tid & 63, ty = tid >> 6;    // ty in [0,8)
    int ybase = ty * 8;
    u64 acc[8];
#pragma unroll
    for (int j = 0; j < 8; j++) acc[j] = 0ull;

#pragma unroll
    for (int iy = 0; iy < 12; iy++) {
        const u64* row = &xsm[(ybase + iy) * 68 + tx];
        u64 v0 = row[0], v1 = row[1], v2 = row[2], v3 = row[3], v4 = row[4];
#pragma unroll
        for (int kh = 0; kh < 5; kh++) {
            int j = iy - kh;
            if (j >= 0 && j < 8) {
                FMA2(acc[j], v0, k2[kh * 5 + 0]);
                FMA2(acc[j], v1, k2[kh * 5 + 1]);
                FMA2(acc[j], v2, k2[kh * 5 + 2]);
                FMA2(acc[j], v3, k2[kh * 5 + 3]);
                FMA2(acc[j], v4, k2[kh * 5 + 4]);
            }
        }
    }
    float* dst0 = &g_sa[((size_t)n * 32 + 2 * p) * 4096 + tx];
    float* dst1 = dst0 + 4096;
#pragma unroll
    for (int j = 0; j < 8; j++) {
        unsigned lo, hi;
        UNPACK2(lo, hi, acc[j]);
        dst0[(ybase + j) * 64] = __uint_as_float(lo);
        dst1[(ybase + j) * 64] = __uint_as_float(hi);
    }
}

// =================== mp1: 32->32, k3, p1, relu ===================
__global__ void __launch_bounds__(256, 2)
mp1_kernel(const float* __restrict__ w, const float* __restrict__ b) {
    __shared__ __align__(16) float sIn[2][18 * 34];
    __shared__ __align__(16) float sW[2][288];
    __shared__ __align__(8) float sB[32];
    int n = blockIdx.z;
    int ox0 = blockIdx.x * 32, oy0 = blockIdx.y * 16;
    int tid = threadIdx.x;
    int ox = tid & 31, oyr = tid >> 5;
    if (tid < 32) sB[tid] = b[tid];

    int iy0 = oy0 - 1, ix0 = ox0 - 1;

    float pin[3], pw[2];
    {
        const float* src = &g_sa[(n * 32 + 0) * 4096];
#pragma unroll
        for (int j = 0; j < 3; j++) {
            int i = tid + j * 256; float v = 0.f;
            if (i < 612) {
                int iy = i / 34, ix = i % 34;
                int gy = iy0 + iy, gx = ix0 + ix;
                if ((unsigned)gy < 64u && (unsigned)gx < 64u) v = src[gy * 64 + gx];
            }
            pin[j] = v;
        }
#pragma unroll
        for (int j = 0; j < 2; j++) {
            int i = tid + j * 256; float v = 0.f;
            if (i < 288) { int o = i & 31, tap = i >> 5; v = w[(o * 32 + 0) * 9 + tap]; }
            pw[j] = v;
        }
    }
#pragma unroll
    for (int j = 0; j < 3; j++) { int i = tid + j * 256; if (i < 612) sIn[0][i] = pin[j]; }
#pragma unroll
    for (int j = 0; j < 2; j++) { int i = tid + j * 256; if (i < 288) sW[0][i] = pw[j]; }
    __syncthreads();

    u64 accA[16], accB[16];
    const u64* sB2 = (const u64*)sB;
#pragma unroll
    for (int o = 0; o < 16; o++) { accA[o] = sB2[o]; accB[o] = sB2[o]; }

    for (int ic = 0; ic < 32; ic++) {
        int cur = ic & 1;
        if (ic < 31) {
            const float* src = &g_sa[(n * 32 + ic + 1) * 4096];
#pragma unroll
            for (int j = 0; j < 3; j++) {
                int i = tid + j * 256; float v = 0.f;
                if (i < 612) {
                    int iy = i / 34, ix = i % 34;
                    int gy = iy0 + iy, gx = ix0 + ix;
                    if ((unsigned)gy < 64u && (unsigned)gx < 64u) v = src[gy * 64 + gx];
                }
                pin[j] = v;
            }
#pragma unroll
            for (int j = 0; j < 2; j++) {
                int i = tid + j * 256; float v = 0.f;
                if (i < 288) { int o = i & 31, tap = i >> 5; v = w[(o * 32 + ic + 1) * 9 + tap]; }
                pw[j] = v;
            }
        }
#pragma unroll
        for (int kh = 0; kh < 3; kh++) {
            const float* rA = &sIn[cur][(oyr + kh) * 34 + ox];
            const float* rB = rA + 8 * 34;
#pragma unroll
            for (int kw = 0; kw < 3; kw++) {
                u64 vA2 = pack_dup(rA[kw]);
                u64 vB2 = pack_dup(rB[kw]);
                const ulonglong2* wq = (const ulonglong2*)&sW[cur][(kh * 3 + kw) * 32];
#pragma unroll
                for (int o2 = 0; o2 < 8; o2++) {
                    ulonglong2 ww = wq[o2];
                    FMA2(accA[2 * o2], vA2, ww.x);
                    FMA2(accA[2 * o2 + 1], vA2, ww.y);
                    FMA2(accB[2 * o2], vB2, ww.x);
                    FMA2(accB[2 * o2 + 1], vB2, ww.y);
                }
            }
        }
        if (ic < 31) {
#pragma unroll
            for (int j = 0; j < 3; j++) { int i = tid + j * 256; if (i < 612) sIn[1 - cur][i] = pin[j]; }
#pragma unroll
            for (int j = 0; j < 2; j++) { int i = tid + j * 256; if (i < 288) sW[1 - cur][i] = pw[j]; }
        }
        __syncthreads();
    }

    int gyA = oy0 + oyr, gyB = gyA + 8, gx = ox0 + ox;
#pragma unroll
    for (int o = 0; o < 16; o++) {
        unsigned lo, hi;
        UNPACK2(lo, hi, accA[o]);
        g_f[((n * 32 + 2 * o) * 64 + gyA) * 64 + gx] = fmaxf(__uint_as_float(lo), 0.f);
        g_f[((n * 32 + 2 * o + 1) * 64 + gyA) * 64 + gx] = fmaxf(__uint_as_float(hi), 0.f);
        UNPACK2(lo, hi, accB[o]);
        g_f[((n * 32 + 2 * o) * 64 + gyB) * 64 + gx] = fmaxf(__uint_as_float(lo), 0.f);
        g_f[((n * 32 + 2 * o + 1) * 64 + gyB) * 64 + gx] = fmaxf(__uint_as_float(hi), 0.f);
    }
}

// =================== mp2: 32->2, k3, p1 (2 px/thread) ===================
__global__ void __launch_bounds__(256, 2)
mp2_kernel(const float* __restrict__ w, const float* __restrict__ b,
           float* __restrict__ out) {
    __shared__ __align__(8) float sIn[2][18 * 34];
    __shared__ __align__(8) float sW[2][18];
    int n = blockIdx.z;
    int ox0 = blockIdx.x * 32, oy0 = blockIdx.y * 16;
    int tid = threadIdx.x;
    int ox = tid & 31, oyr = tid >> 5;

    int iy0 = oy0 - 1, ix0 = ox0 - 1;

    float pin[3], pwv;
    {
        const float* src = &g_f[(n * 32 + 0) * 4096];
#pragma unroll
        for (int j = 0; j < 3; j++) {
            int i = tid + j * 256; float v = 0.f;
            if (i < 612) {
                int iy = i / 34, ix = i % 34;
                int gy = iy0 + iy, gx = ix0 + ix;
                if ((unsigned)gy < 64u && (unsigned)gx < 64u) v = src[gy * 64 + gx];
            }
            pin[j] = v;
        }
        pwv = (tid < 18) ? w[((tid & 1) * 32 + 0) * 9 + (tid >> 1)] : 0.f;
    }
#pragma unroll
    for (int j = 0; j < 3; j++) { int i = tid + j * 256; if (i < 612) sIn[0][i] = pin[j]; }
    if (tid < 18) sW[0][tid] = pwv;
    __syncthreads();

    u64 accA2, accB2;
    PACK2(accA2, __float_as_uint(b[0]), __float_as_uint(b[1]));
    accB2 = accA2;

    for (int ic = 0; ic < 32; ic++) {
        int cur = ic & 1;
        if (ic < 31) {
            const float* src = &g_f[(n * 32 + ic + 1) * 4096];
#pragma unroll
            for (int j = 0; j < 3; j++) {
                int i = tid + j * 256; float v = 0.f;
                if (i < 612) {
                    int iy = i / 34, ix = i % 34;
                    int gy = iy0 + iy, gx = ix0 + ix;
                    if ((unsigned)gy < 64u && (unsigned)gx < 64u) v = src[gy * 64 + gx];
                }
                pin[j] = v;
            }
            pwv = (tid < 18) ? w[((tid & 1) * 32 + ic + 1) * 9 + (tid >> 1)] : 0.f;
        }
        const u64* wp2 = (const u64*)&sW[cur][0];
#pragma unroll
        for (int kh = 0; kh < 3; kh++) {
            const float* rA = &sIn[cur][(oyr + kh) * 34 + ox];
            const float* rB = rA + 8 * 34;
#pragma unroll
            for (int kw = 0; kw < 3; kw++) {
                u64 w2 = wp2[kh * 3 + kw];
                FMA2(accA2, pack_dup(rA[kw]), w2);
                FMA2(accB2, pack_dup(rB[kw]), w2);
            }
        }
        if (ic < 31) {
#pragma unroll
            for (int j = 0; j < 3; j++) { int i = tid + j * 256; if (i < 612) sIn[1 - cur][i] = pin[j]; }
            if (tid < 18) sW[1 - cur][tid] = pwv;
        }
        __syncthreads();
    }
    int gyA = oy0 + oyr, gyB = gyA + 8, gx = ox0 + ox;
    unsigned lo, hi;
    UNPACK2(lo, hi, accA2);
    out[((n * 2 + 0) * 64 + gyA) * 64 + gx] = __uint_as_float(lo);
    out[((n * 2 + 1) * 64 + gyA) * 64 + gx] = __uint_as_float(hi);
    UNPACK2(lo, hi, accB2);
    out[((n * 2 + 0) * 64 + gyB) * 64 + gx] = __uint_as_float(lo);
    out[((n * 2 + 1) * 64 + gyB) * 64 + gx] = __uint_as_float(hi);
}

// =================== launch ===================
extern "C" void kernel_launch(void* const* d_in, const int* in_sizes, int n_in,
                              void* d_out, int out_size) {
    const float* images = (const float*)d_in[0];
    const float* actions = (const float*)d_in[1];
    const float* pe_w1 = (const float*)d_in[2];
    const float* pe_b1 = (const float*)d_in[3];
    const float* pe_w2 = (const float*)d_in[4];
    const float* pe_b2 = (const float*)d_in[5];
    const float* ae_w1 = (const float*)d_in[6];
    const float* ae_b1 = (const float*)d_in[7];
    const float* ae_w2 = (const float*)d_in[8];
    const float* ae_b2 = (const float*)d_in[9];
    const float* mp_w1 = (const float*)d_in[10];
    const float* mp_b1 = (const float*)d_in[11];
    const float* mp_w2 = (const float*)d_in[12];
    const float* mp_b2 = (const float*)d_in[13];
    float* out = (float*)d_out;

    ae_kernel<<<NB, 256>>>(actions, ae_w1, ae_b1, ae_w2, ae_b2);
    conv1_kernel<<<dim3(4, 8, NB), 256>>>(images, pe_w1, pe_b1);
    conv2_kernel<<<dim3(2, 4, NB), 256>>>(pe_w2, pe_b2);
    xconv_kernel<<<dim3(16, NB), 512, XC_SMEM>>>();
    mp1_kernel<<<dim3(2, 4, NB), 256>>>(mp_w1, mp_b1);
    mp2_kernel<<<dim3(2, 4, NB), 256>>>(mp_w2, mp_b2, out);
}